// round 7
// baseline (speedup 1.0000x reference)
#include <cuda_runtime.h>
#include <cuda_bf16.h>
#include <math.h>

// Problem shape (fixed by setup_inputs)
#define N     2048
#define C     256
#define NCLS  8
#define KSEL  20
#define MAXC  384      // class size bound; tiles cover 6*64=384
#define EPS   1e-6f

typedef unsigned long long u64;

// Scratch (static __device__ — no allocations)
// g_D layout: [2 channel-halves][N rows (original index)][MAXC positions]
__device__ float g_D[2ull * N * MAXC];
__device__ int   g_orderC[NCLS * MAXC];   // per-class member lists (original indices)
__device__ int   g_cntC[NCLS];
__device__ float g_partial[256];
__device__ unsigned int g_counter;

__device__ __forceinline__ float finf() { return __int_as_float(0x7f800000); }

__device__ __forceinline__ u64 addx2(u64 a, u64 b) {
    u64 r;
    asm("add.rn.f32x2 %0, %1, %2;" : "=l"(r) : "l"(a), "l"(b));
    return r;
}

// ---------------------------------------------------------------------------
// Kernel 1: class-blocked pairwise L1 distance, packed f32x2, channel-split.
// 256 threads, 4x4 micro-tile, KC=64 single buffer (4 syncs), no live
// prefetch registers (fits 85-reg cap of occupancy 3 without spills).
// Early count-based exit for non-working tiles.
// ---------------------------------------------------------------------------
#define TB 64
#define KC 64   // channels per smem chunk (32 packed pairs)

__global__ __launch_bounds__(256, 3)
void dist_kernel(const float* __restrict__ feat, const int* __restrict__ target) {
    int bid = blockIdx.x;
    if (bid == 0 && threadIdx.x == 0) g_counter = 0u;   // reset for topk

    int cs  = (bid >= 288) ? 1 : 0;    // channel half
    int b   = bid - cs * 288;
    int cls, x, y;
    if (b < 200) {                      // 5x5 working region first
        cls = b / 25; int r = b % 25; x = r % 5; y = r / 5;
    } else {                            // 6x6 fringe (x==5 or y==5)
        int e = b - 200; cls = e / 11; int r = e % 11;
        if (r < 6) { x = 5; y = r; } else { x = r - 6; y = 5; }
    }

    // ---- smem (tile arrays MUST be 16B-aligned: ulonglong2 loads) ----
    __shared__ __align__(16) float As2[KC / 2][TB][2];   // (a + eps), pair packed
    __shared__ __align__(16) float Bs2[KC / 2][TB][2];   // (-b), pair packed
    __shared__ __align__(16) int   list[MAXC];
    __shared__ int   s_wofs[8];
    __shared__ int   s_cnt;

    int t    = threadIdx.x;
    int lane = t & 31;
    int w    = t >> 5;

    // ---- cheap count first: early-exit for non-working tiles ----
    int4 t0 = *(const int4*)(target + t * 8);
    int4 t1 = *(const int4*)(target + t * 8 + 4);
    int tg[8] = {t0.x, t0.y, t0.z, t0.w, t1.x, t1.y, t1.z, t1.w};
    int mcount = 0;
#pragma unroll
    for (int u = 0; u < 8; u++) mcount += (tg[u] == cls);

    int red = mcount;
#pragma unroll
    for (int o = 16; o > 0; o >>= 1) red += __shfl_down_sync(0xffffffffu, red, o);
    if (lane == 0) s_wofs[w] = red;
    __syncthreads();
    if (t == 0) {
        int acc = 0;
#pragma unroll
        for (int ww = 0; ww < 8; ww++) acc += s_wofs[ww];
        s_cnt = acc;
    }
    __syncthreads();
    int cnt = min(s_cnt, MAXC);

    int ti0 = y * TB;
    int tj0 = x * TB;
    if (ti0 >= cnt || tj0 >= cnt) return;   // publishers (x=0,y=0) always pass

    // ---- full stable compaction (working blocks only) ----
    int incl = mcount;
#pragma unroll
    for (int o = 1; o < 32; o <<= 1) {
        int v = __shfl_up_sync(0xffffffffu, incl, o);
        if (lane >= o) incl += v;
    }
    if (lane == 31) s_wofs[w] = incl;
    __syncthreads();
    if (t == 0) {
        int acc = 0;
#pragma unroll
        for (int ww = 0; ww < 8; ww++) { int v = s_wofs[ww]; s_wofs[ww] = acc; acc += v; }
    }
    __syncthreads();
    int base = s_wofs[w] + incl - mcount;   // exclusive prefix for this thread
#pragma unroll
    for (int u = 0; u < 8; u++) {
        if (tg[u] == cls && base < MAXC) { list[base] = t * 8 + u; base++; }
    }
    __syncthreads();
    for (int p = cnt + t; p < MAXC; p += 256) list[p] = 0;   // safe padding
    __syncthreads();

    // publisher blocks export the list for topk (one block per class, cs==0)
    if (cs == 0 && x == 0 && y == 0) {
        if (t == 0) g_cntC[cls] = cnt;
        for (int p = t; p < cnt; p += 256) g_orderC[cls * MAXC + p] = list[p];
    }

    int tx = t & 15;      // j-group: 4 cols
    int ty = t >> 4;      // i-group: 4 rows

    u64 acc2[16];
#pragma unroll
    for (int q = 0; q < 16; q++) acc2[q] = 0ull;

    // staging assignment: thread t loads row lr, 16 channels starting at lc
    int lr = t >> 2;            // 0..63
    int lc = (t & 3) * 16;      // 0,16,32,48
    int gi = ti0 + lr, gj = tj0 + lr;
    bool av = gi < cnt, bv = gj < cnt;
    const float* arow = feat + (size_t)(av ? list[gi] : 0) * C;
    const float* brow = feat + (size_t)(bv ? list[gj] : 0) * C;

    int cbase = cs * 128;
#pragma unroll
    for (int ch = 0; ch < 2; ch++) {
        __syncthreads();   // previous chunk's compute done before overwrite
        {
            float4 z4 = make_float4(0.f, 0.f, 0.f, 0.f);
            int cc = cbase + ch * KC + lc;
#pragma unroll
            for (int h = 0; h < 2; h++) {
                float4 pa0 = z4, pa1 = z4, pb0 = z4, pb1 = z4;
                if (av) {
                    pa0 = *(const float4*)(arow + cc + h * 8);
                    pa1 = *(const float4*)(arow + cc + h * 8 + 4);
                }
                if (bv) {
                    pb0 = *(const float4*)(brow + cc + h * 8);
                    pb1 = *(const float4*)(brow + cc + h * 8 + 4);
                }
                int p = (lc + h * 8) >> 1;
                *(float2*)&As2[p + 0][lr][0] = make_float2(pa0.x + EPS, pa0.y + EPS);
                *(float2*)&As2[p + 1][lr][0] = make_float2(pa0.z + EPS, pa0.w + EPS);
                *(float2*)&As2[p + 2][lr][0] = make_float2(pa1.x + EPS, pa1.y + EPS);
                *(float2*)&As2[p + 3][lr][0] = make_float2(pa1.z + EPS, pa1.w + EPS);
                *(float2*)&Bs2[p + 0][lr][0] = make_float2(-pb0.x, -pb0.y);
                *(float2*)&Bs2[p + 1][lr][0] = make_float2(-pb0.z, -pb0.w);
                *(float2*)&Bs2[p + 2][lr][0] = make_float2(-pb1.x, -pb1.y);
                *(float2*)&Bs2[p + 3][lr][0] = make_float2(-pb1.z, -pb1.w);
            }
        }
        __syncthreads();

#pragma unroll
        for (int kk2 = 0; kk2 < KC / 2; kk2++) {
            ulonglong2 aL = *(const ulonglong2*)&As2[kk2][ty * 4][0];
            ulonglong2 aH = *(const ulonglong2*)&As2[kk2][ty * 4 + 2][0];
            ulonglong2 bL = *(const ulonglong2*)&Bs2[kk2][tx * 4][0];
            ulonglong2 bH = *(const ulonglong2*)&Bs2[kk2][tx * 4 + 2][0];
            u64 a2[4] = {aL.x, aL.y, aH.x, aH.y};
            u64 b2[4] = {bL.x, bL.y, bH.x, bH.y};
#pragma unroll
            for (int ii = 0; ii < 4; ii++)
#pragma unroll
                for (int jj = 0; jj < 4; jj++) {
                    u64 d = addx2(a2[ii], b2[jj]);          // a + eps - b
                    d &= 0x7FFFFFFF7FFFFFFFull;             // packed |.|
                    acc2[ii * 4 + jj] = addx2(acc2[ii * 4 + jj], d);
                }
        }
    }

    float* dhalf = g_D + (size_t)cs * N * MAXC;
#pragma unroll
    for (int ii = 0; ii < 4; ii++) {
        int ti = ti0 + ty * 4 + ii;
        if (ti >= cnt) continue;
        float o[4];
#pragma unroll
        for (int jj = 0; jj < 4; jj++) {
            u64 a = acc2[ii * 4 + jj];
            float lo = __uint_as_float((unsigned)(a & 0xFFFFFFFFull));
            float hi = __uint_as_float((unsigned)(a >> 32));
            int tj = tj0 + tx * 4 + jj;
            o[jj] = (ti == tj) ? finf() : (lo + hi);
        }
        *(float4*)(dhalf + (size_t)list[ti] * MAXC + tj0 + tx * 4) =
            make_float4(o[0], o[1], o[2], o[3]);
    }
}

// ---------------------------------------------------------------------------
// Kernel 2: fused top-K + neighbor MSE + CE + final reduction (last block).
// One warp per row. Packed keys, argmin-4 rounds (bitonic lowest-4 merge):
// 5 rounds pick 4 winners each. NO register cap (grid can't fill SMs anyway).
// ---------------------------------------------------------------------------
__device__ __forceinline__ void ce_swap(unsigned &a, unsigned &b) {
    unsigned lo = min(a, b), hi = max(a, b);
    a = lo; b = hi;
}

__global__ __launch_bounds__(256)
void topk_loss_kernel(const float* __restrict__ feat,
                      const float* __restrict__ scores,
                      const int* __restrict__ target,
                      float* __restrict__ out) {
    __shared__ float s_part[8];
    __shared__ bool  s_last;

    int warp = threadIdx.x >> 5;
    int lane = threadIdx.x & 31;
    int i = blockIdx.x * 8 + warp;

    int cls = target[i];
    int cnt = min(g_cntC[cls], MAXC);
    const int* order = g_orderC + cls * MAXC;
    int m = min(cnt - 1, KSEL);

    float rowloss = 0.f;
    if (m > 0) {
        const float* d0 = g_D + (size_t)i * MAXC;
        const float* d1 = g_D + (size_t)(N + i) * MAXC;

        // packed keys: high 23 bits of distance | 9-bit position (unique)
        unsigned v[12];
#pragma unroll
        for (int s = 0; s < 12; s++) {
            int p = s * 32 + lane;
            if (p < cnt) {
                float d = d0[p] + d1[p];
                v[s] = (__float_as_uint(d) & 0xFFFFFE00u) | (unsigned)p;
            } else {
                v[s] = 0xFFFFFFFFu;
            }
        }

        unsigned mypos = 511u;
#pragma unroll
        for (int r = 0; r < 5; r++) {
            // local sorted 4-smallest of my 12 slots
            unsigned a0 = 0xFFFFFFFFu, a1 = 0xFFFFFFFFu,
                     a2 = 0xFFFFFFFFu, a3 = 0xFFFFFFFFu;
#pragma unroll
            for (int s = 0; s < 12; s++) {
                unsigned xv = v[s];
                a3 = min(a3, xv);
                ce_swap(a2, a3);
                ce_swap(a1, a2);
                ce_swap(a0, a1);
            }
            // warp merge: lowest-4 of two sorted lists via bitonic trick
#pragma unroll
            for (int o = 16; o > 0; o >>= 1) {
                unsigned b0 = __shfl_down_sync(0xffffffffu, a0, o);
                unsigned b1 = __shfl_down_sync(0xffffffffu, a1, o);
                unsigned b2 = __shfl_down_sync(0xffffffffu, a2, o);
                unsigned b3 = __shfl_down_sync(0xffffffffu, a3, o);
                unsigned c0 = min(a0, b3);
                unsigned c1 = min(a1, b2);
                unsigned c2 = min(a2, b1);
                unsigned c3 = min(a3, b0);
                // c is bitonic -> sort with 4 compare-exchanges
                ce_swap(c0, c2); ce_swap(c1, c3);
                ce_swap(c0, c1); ce_swap(c2, c3);
                a0 = c0; a1 = c1; a2 = c2; a3 = c3;
            }
            unsigned w0 = __shfl_sync(0xffffffffu, a0, 0);
            unsigned w1 = __shfl_sync(0xffffffffu, a1, 0);
            unsigned w2 = __shfl_sync(0xffffffffu, a2, 0);
            unsigned w3 = __shfl_sync(0xffffffffu, a3, 0);
            if (lane == 4 * r)     mypos = w0 & 511u;
            if (lane == 4 * r + 1) mypos = w1 & 511u;
            if (lane == 4 * r + 2) mypos = w2 & 511u;
            if (lane == 4 * r + 3) mypos = w3 & 511u;
#pragma unroll
            for (int s = 0; s < 12; s++) {
                unsigned xv = v[s];
                if (xv == w0 || xv == w1 || xv == w2 || xv == w3)
                    v[s] = 0xFFFFFFFFu;
            }
        }

        // resolve neighbor original index per lane (20 parallel loads)
        unsigned cp = min(mypos, (unsigned)(MAXC - 1));
        int myj = order[cp];

        // MSE gather: lane owns 8 channels; pre-resolved j broadcast per k.
        float inv_m = 1.0f / (float)m;
        const float* xi = feat + (size_t)i * C + lane * 8;
        float4 x0 = *(const float4*)(xi);
        float4 x1 = *(const float4*)(xi + 4);
        float acc = 0.f;
#pragma unroll
        for (int k = 0; k < KSEL; k++) {
            bool valid = (k < m);
            int j = __shfl_sync(0xffffffffu, myj, k);
            const float* xj = feat + (size_t)j * C + lane * 8;
            float4 a0 = *(const float4*)(xj);
            float4 a1 = *(const float4*)(xj + 4);
            float s = 0.f, d;
            d = x0.x - a0.x * inv_m; s += d * d;
            d = x0.y - a0.y * inv_m; s += d * d;
            d = x0.z - a0.z * inv_m; s += d * d;
            d = x0.w - a0.w * inv_m; s += d * d;
            d = x1.x - a1.x * inv_m; s += d * d;
            d = x1.y - a1.y * inv_m; s += d * d;
            d = x1.z - a1.z * inv_m; s += d * d;
            d = x1.w - a1.w * inv_m; s += d * d;
            acc += valid ? s : 0.f;
        }
#pragma unroll
        for (int o = 16; o > 0; o >>= 1)
            acc += __shfl_down_sync(0xffffffffu, acc, o);
        rowloss = acc;
    }

    // per-row CE (lane 0), combine with lam term
    if (lane == 0) {
        float4 s0 = *(const float4*)(scores + (size_t)i * NCLS);
        float4 s1 = *(const float4*)(scores + (size_t)i * NCLS + 4);
        float sv[8] = {s0.x, s0.y, s0.z, s0.w, s1.x, s1.y, s1.z, s1.w};
        float mx = sv[0];
#pragma unroll
        for (int c = 1; c < 8; c++) mx = fmaxf(mx, sv[c]);
        float se = 0.f;
#pragma unroll
        for (int c = 0; c < 8; c++) se += __expf(sv[c] - mx);
        float ce = (mx + __logf(se)) - sv[cls];
        s_part[warp] = ce * (1.0f / (float)N) + 25.0f * rowloss;  // LAM*0.5 = 25
    }
    __syncthreads();

    if (threadIdx.x == 0) {
        float p = 0.f;
#pragma unroll
        for (int w = 0; w < 8; w++) p += s_part[w];
        g_partial[blockIdx.x] = p;
        __threadfence();
        unsigned int done = atomicAdd(&g_counter, 1u);
        s_last = (done == 255u);
    }
    __syncthreads();

    if (s_last) {
        __shared__ float sred[256];
        int t = threadIdx.x;
        sred[t] = g_partial[t];
        __syncthreads();
        for (int o = 128; o > 0; o >>= 1) {
            if (t < o) sred[t] += sred[t + o];
            __syncthreads();
        }
        if (t == 0) out[0] = sred[0];
    }
}

// ---------------------------------------------------------------------------
extern "C" void kernel_launch(void* const* d_in, const int* in_sizes, int n_in,
                              void* d_out, int out_size) {
    const float* feature = (const float*)d_in[0];   // [2048, 256]
    const float* scores  = (const float*)d_in[1];   // [2048, 8]
    const int*   target  = (const int*)d_in[2];     // [2048]
    float* out = (float*)d_out;

    dist_kernel<<<576, 256>>>(feature, target);
    topk_loss_kernel<<<N / 8, 256>>>(feature, scores, target, out);
}

// round 8
// speedup vs baseline: 1.0823x; 1.0823x over previous
#include <cuda_runtime.h>
#include <cuda_bf16.h>
#include <math.h>

// Problem shape (fixed by setup_inputs)
#define N     2048
#define C     256
#define NCLS  8
#define KSEL  20
#define MAXC  384      // class size bound; tiles cover 6*64=384
#define EPS   1e-6f

typedef unsigned long long u64;

// Scratch (static __device__ — no allocations)
// g_D layout: [4 channel-quarters][N rows (original index)][MAXC positions]
__device__ float g_D[4ull * N * MAXC];
__device__ int   g_orderC[NCLS * MAXC];   // per-class member lists (original indices)
__device__ int   g_cntC[NCLS];
__device__ float g_partial[256];
__device__ unsigned int g_counter;

__device__ __forceinline__ float finf() { return __int_as_float(0x7f800000); }

__device__ __forceinline__ u64 addx2(u64 a, u64 b) {
    u64 r;
    asm("add.rn.f32x2 %0, %1, %2;" : "=l"(r) : "l"(a), "l"(b));
    return r;
}

// ---------------------------------------------------------------------------
// Kernel 1: class-blocked pairwise L1 distance, packed f32x2, channel-QUARTER
// split. 256 threads, 4x4 micro-tile, KC=64 = whole quarter in one smem chunk
// -> exactly ONE mainloop barrier. ~512 working blocks (3.5/SM) for balance.
// Grid: 1152 = 4 quarters x (8 classes x 36 tiles), 5x5 working region first.
// ---------------------------------------------------------------------------
#define TB 64
#define KC 64   // channels per chunk == quarter size (32 packed pairs)

__global__ __launch_bounds__(256, 3)
void dist_kernel(const float* __restrict__ feat, const int* __restrict__ target) {
    int bid = blockIdx.x;
    if (bid == 0 && threadIdx.x == 0) g_counter = 0u;   // reset for topk

    int cs  = bid / 288;               // channel quarter 0..3
    int b   = bid - cs * 288;
    int cls, x, y;
    if (b < 200) {                      // 5x5 working region first
        cls = b / 25; int r = b % 25; x = r % 5; y = r / 5;
    } else {                            // 6x6 fringe (x==5 or y==5)
        int e = b - 200; cls = e / 11; int r = e % 11;
        if (r < 6) { x = 5; y = r; } else { x = r - 6; y = 5; }
    }

    // ---- smem (tile arrays MUST be 16B-aligned: ulonglong2 loads) ----
    __shared__ __align__(16) float As2[KC / 2][TB][2];   // (a + eps), pair packed
    __shared__ __align__(16) float Bs2[KC / 2][TB][2];   // (-b), pair packed
    __shared__ __align__(16) int   list[MAXC];
    __shared__ int   s_wofs[8];
    __shared__ int   s_cnt;

    int t    = threadIdx.x;
    int lane = t & 31;
    int w    = t >> 5;

    // ---- cheap count first: early-exit for non-working tiles ----
    int4 t0 = *(const int4*)(target + t * 8);
    int4 t1 = *(const int4*)(target + t * 8 + 4);
    int tg[8] = {t0.x, t0.y, t0.z, t0.w, t1.x, t1.y, t1.z, t1.w};
    int mcount = 0;
#pragma unroll
    for (int u = 0; u < 8; u++) mcount += (tg[u] == cls);

    int red = mcount;
#pragma unroll
    for (int o = 16; o > 0; o >>= 1) red += __shfl_down_sync(0xffffffffu, red, o);
    if (lane == 0) s_wofs[w] = red;
    __syncthreads();
    if (t == 0) {
        int acc = 0;
#pragma unroll
        for (int ww = 0; ww < 8; ww++) acc += s_wofs[ww];
        s_cnt = acc;
    }
    __syncthreads();
    int cnt = min(s_cnt, MAXC);

    int ti0 = y * TB;
    int tj0 = x * TB;
    if (ti0 >= cnt || tj0 >= cnt) return;   // publishers (x=0,y=0) always pass

    // ---- full stable compaction (working blocks only) ----
    int incl = mcount;
#pragma unroll
    for (int o = 1; o < 32; o <<= 1) {
        int v = __shfl_up_sync(0xffffffffu, incl, o);
        if (lane >= o) incl += v;
    }
    if (lane == 31) s_wofs[w] = incl;
    __syncthreads();
    if (t == 0) {
        int acc = 0;
#pragma unroll
        for (int ww = 0; ww < 8; ww++) { int v = s_wofs[ww]; s_wofs[ww] = acc; acc += v; }
    }
    __syncthreads();
    int base = s_wofs[w] + incl - mcount;   // exclusive prefix for this thread
#pragma unroll
    for (int u = 0; u < 8; u++) {
        if (tg[u] == cls && base < MAXC) { list[base] = t * 8 + u; base++; }
    }
    __syncthreads();
    for (int p = cnt + t; p < MAXC; p += 256) list[p] = 0;   // safe padding
    __syncthreads();

    // publisher blocks export the list for topk (one block per class, cs==0)
    if (cs == 0 && x == 0 && y == 0) {
        if (t == 0) g_cntC[cls] = cnt;
        for (int p = t; p < cnt; p += 256) g_orderC[cls * MAXC + p] = list[p];
    }

    int tx = t & 15;      // j-group: 4 cols
    int ty = t >> 4;      // i-group: 4 rows

    u64 acc2[16];
#pragma unroll
    for (int q = 0; q < 16; q++) acc2[q] = 0ull;

    // staging: thread t loads row lr, 16 channels at lc (4x4 threads per row)
    int lr = t >> 2;            // 0..63
    int lc = (t & 3) * 16;      // 0,16,32,48
    int gi = ti0 + lr, gj = tj0 + lr;
    // clamped: rows beyond cnt read row list[..]=0 (garbage discarded at store)
    const float* arow = feat + (size_t)list[min(gi, MAXC - 1)] * C;
    const float* brow = feat + (size_t)list[min(gj, MAXC - 1)] * C;

    int cbase = cs * 64;
    {
        int cc = cbase + lc;
#pragma unroll
        for (int h = 0; h < 2; h++) {
            float4 pa0 = *(const float4*)(arow + cc + h * 8);
            float4 pa1 = *(const float4*)(arow + cc + h * 8 + 4);
            float4 pb0 = *(const float4*)(brow + cc + h * 8);
            float4 pb1 = *(const float4*)(brow + cc + h * 8 + 4);
            int p = (lc + h * 8) >> 1;
            *(float2*)&As2[p + 0][lr][0] = make_float2(pa0.x + EPS, pa0.y + EPS);
            *(float2*)&As2[p + 1][lr][0] = make_float2(pa0.z + EPS, pa0.w + EPS);
            *(float2*)&As2[p + 2][lr][0] = make_float2(pa1.x + EPS, pa1.y + EPS);
            *(float2*)&As2[p + 3][lr][0] = make_float2(pa1.z + EPS, pa1.w + EPS);
            *(float2*)&Bs2[p + 0][lr][0] = make_float2(-pb0.x, -pb0.y);
            *(float2*)&Bs2[p + 1][lr][0] = make_float2(-pb0.z, -pb0.w);
            *(float2*)&Bs2[p + 2][lr][0] = make_float2(-pb1.x, -pb1.y);
            *(float2*)&Bs2[p + 3][lr][0] = make_float2(-pb1.z, -pb1.w);
        }
    }
    __syncthreads();   // the ONLY mainloop barrier

#pragma unroll
    for (int kk2 = 0; kk2 < KC / 2; kk2++) {
        ulonglong2 aL = *(const ulonglong2*)&As2[kk2][ty * 4][0];
        ulonglong2 aH = *(const ulonglong2*)&As2[kk2][ty * 4 + 2][0];
        ulonglong2 bL = *(const ulonglong2*)&Bs2[kk2][tx * 4][0];
        ulonglong2 bH = *(const ulonglong2*)&Bs2[kk2][tx * 4 + 2][0];
        u64 a2[4] = {aL.x, aL.y, aH.x, aH.y};
        u64 b2[4] = {bL.x, bL.y, bH.x, bH.y};
#pragma unroll
        for (int ii = 0; ii < 4; ii++)
#pragma unroll
            for (int jj = 0; jj < 4; jj++) {
                u64 d = addx2(a2[ii], b2[jj]);          // a + eps - b
                d &= 0x7FFFFFFF7FFFFFFFull;             // packed |.|
                acc2[ii * 4 + jj] = addx2(acc2[ii * 4 + jj], d);
            }
    }

    float* dq = g_D + (size_t)cs * N * MAXC;
#pragma unroll
    for (int ii = 0; ii < 4; ii++) {
        int ti = ti0 + ty * 4 + ii;
        if (ti >= cnt) continue;
        float o[4];
#pragma unroll
        for (int jj = 0; jj < 4; jj++) {
            u64 a = acc2[ii * 4 + jj];
            float lo = __uint_as_float((unsigned)(a & 0xFFFFFFFFull));
            float hi = __uint_as_float((unsigned)(a >> 32));
            int tj = tj0 + tx * 4 + jj;
            o[jj] = (ti == tj) ? finf() : (lo + hi);
        }
        *(float4*)(dq + (size_t)list[ti] * MAXC + tj0 + tx * 4) =
            make_float4(o[0], o[1], o[2], o[3]);
    }
}

// ---------------------------------------------------------------------------
// Kernel 2: fused top-K + neighbor MSE + CE + final reduction (last block).
// One warp per row. EXACT Round-6 structure (measured 13.7us): packed keys,
// argmin-2 rounds, per-lane parallel neighbor index resolve, (256,2) bounds.
// Only change: sums 4 distance quarters.
// ---------------------------------------------------------------------------
__global__ __launch_bounds__(256, 2)
void topk_loss_kernel(const float* __restrict__ feat,
                      const float* __restrict__ scores,
                      const int* __restrict__ target,
                      float* __restrict__ out) {
    __shared__ float s_part[8];
    __shared__ bool  s_last;

    int warp = threadIdx.x >> 5;
    int lane = threadIdx.x & 31;
    int i = blockIdx.x * 8 + warp;

    int cls = target[i];
    int cnt = min(g_cntC[cls], MAXC);
    const int* order = g_orderC + cls * MAXC;
    int m = min(cnt - 1, KSEL);

    float rowloss = 0.f;
    if (m > 0) {
        const float* d0 = g_D + (size_t)i * MAXC;
        const float* d1 = g_D + (size_t)(N + i) * MAXC;
        const float* d2 = g_D + (size_t)(2 * N + i) * MAXC;
        const float* d3 = g_D + (size_t)(3 * N + i) * MAXC;

        // packed keys: high 23 bits of distance | 9-bit position
        unsigned v[12];
#pragma unroll
        for (int s = 0; s < 12; s++) {
            int p = s * 32 + lane;
            if (p < cnt) {
                float d = (d0[p] + d1[p]) + (d2[p] + d3[p]);
                v[s] = (__float_as_uint(d) & 0xFFFFFE00u) | (unsigned)p;
            } else {
                v[s] = 0xFFFFFFFFu;
            }
        }

        unsigned mypos = 0;
#pragma unroll
        for (int r = 0; r < 10; r++) {
            // local two smallest of 12 slots
            unsigned k1 = 0xFFFFFFFFu, k2 = 0xFFFFFFFFu;
#pragma unroll
            for (int s = 0; s < 12; s++) {
                unsigned xv = v[s];
                unsigned nk2 = min(k2, max(k1, xv));
                k1 = min(k1, xv);
                k2 = nk2;
            }
            // warp-wide two smallest
#pragma unroll
            for (int o = 16; o > 0; o >>= 1) {
                unsigned p1 = __shfl_down_sync(0xffffffffu, k1, o);
                unsigned p2 = __shfl_down_sync(0xffffffffu, k2, o);
                unsigned hi = max(k1, p1);
                k1 = min(k1, p1);
                k2 = min(hi, min(k2, p2));
            }
            unsigned w1 = __shfl_sync(0xffffffffu, k1, 0);
            unsigned w2 = __shfl_sync(0xffffffffu, k2, 0);
            if (lane == 2 * r)     mypos = w1 & 511u;
            if (lane == 2 * r + 1) mypos = w2 & 511u;
#pragma unroll
            for (int s = 0; s < 12; s++) {
                if (v[s] == w1 || v[s] == w2) v[s] = 0xFFFFFFFFu;
            }
        }

        // resolve neighbor original index per lane (20 parallel loads)
        unsigned cp = min(mypos, (unsigned)(MAXC - 1));
        int myj = order[cp];

        // MSE gather: lane owns 8 channels; pre-resolved j broadcast per k.
        float inv_m = 1.0f / (float)m;
        const float* xi = feat + (size_t)i * C + lane * 8;
        float4 x0 = *(const float4*)(xi);
        float4 x1 = *(const float4*)(xi + 4);
        float acc = 0.f;
#pragma unroll
        for (int k = 0; k < KSEL; k++) {
            bool valid = (k < m);
            int j = __shfl_sync(0xffffffffu, myj, k);
            const float* xj = feat + (size_t)j * C + lane * 8;
            float4 a0 = *(const float4*)(xj);
            float4 a1 = *(const float4*)(xj + 4);
            float s = 0.f, d;
            d = x0.x - a0.x * inv_m; s += d * d;
            d = x0.y - a0.y * inv_m; s += d * d;
            d = x0.z - a0.z * inv_m; s += d * d;
            d = x0.w - a0.w * inv_m; s += d * d;
            d = x1.x - a1.x * inv_m; s += d * d;
            d = x1.y - a1.y * inv_m; s += d * d;
            d = x1.z - a1.z * inv_m; s += d * d;
            d = x1.w - a1.w * inv_m; s += d * d;
            acc += valid ? s : 0.f;
        }
#pragma unroll
        for (int o = 16; o > 0; o >>= 1)
            acc += __shfl_down_sync(0xffffffffu, acc, o);
        rowloss = acc;
    }

    // per-row CE (lane 0), combine with lam term
    if (lane == 0) {
        float4 s0 = *(const float4*)(scores + (size_t)i * NCLS);
        float4 s1 = *(const float4*)(scores + (size_t)i * NCLS + 4);
        float sv[8] = {s0.x, s0.y, s0.z, s0.w, s1.x, s1.y, s1.z, s1.w};
        float mx = sv[0];
#pragma unroll
        for (int c = 1; c < 8; c++) mx = fmaxf(mx, sv[c]);
        float se = 0.f;
#pragma unroll
        for (int c = 0; c < 8; c++) se += __expf(sv[c] - mx);
        float ce = (mx + __logf(se)) - sv[cls];
        s_part[warp] = ce * (1.0f / (float)N) + 25.0f * rowloss;  // LAM*0.5 = 25
    }
    __syncthreads();

    if (threadIdx.x == 0) {
        float p = 0.f;
#pragma unroll
        for (int w = 0; w < 8; w++) p += s_part[w];
        g_partial[blockIdx.x] = p;
        __threadfence();
        unsigned int done = atomicAdd(&g_counter, 1u);
        s_last = (done == 255u);
    }
    __syncthreads();

    if (s_last) {
        __shared__ float sred[256];
        int t = threadIdx.x;
        sred[t] = g_partial[t];
        __syncthreads();
        for (int o = 128; o > 0; o >>= 1) {
            if (t < o) sred[t] += sred[t + o];
            __syncthreads();
        }
        if (t == 0) out[0] = sred[0];
    }
}

// ---------------------------------------------------------------------------
extern "C" void kernel_launch(void* const* d_in, const int* in_sizes, int n_in,
                              void* d_out, int out_size) {
    const float* feature = (const float*)d_in[0];   // [2048, 256]
    const float* scores  = (const float*)d_in[1];   // [2048, 8]
    const int*   target  = (const int*)d_in[2];     // [2048]
    float* out = (float*)d_out;

    dist_kernel<<<1152, 256>>>(feature, target);
    topk_loss_kernel<<<N / 8, 256>>>(feature, scores, target, out);
}